// round 17
// baseline (speedup 1.0000x reference)
#include <cuda_runtime.h>
#include <cuda_bf16.h>
#include <math.h>

#define Bc   8
#define Lc   256
#define Dc   128
#define Hc   4
#define HDc  32
#define NROW (Bc*Lc)      // 2048
#define RQ   8            // rows per block in qkv GEMM
#define RF   4            // rows per block in ffn
#define NTAU 257
#define DQR  1028         // floats per g_dqt row: 4 heads * 257 taus
#define CVTB 129          // blocks for timeV bf16 conversion

#define TQ2  4            // queries per attention block
#define CH   64           // key chunk (pass 1 staging)
#define PADK 132          // floats per padded smem row (33 float4)
#define NEGV (-4294967295.0f)
#define SCALE 0.17677669529663689f
// dyn smem floats: sKV 8448 + sQ 512 + sS 4096 = 13056; ints: tm 1024
#define SMEM_ATTN (13056*4 + 1024*4)

typedef unsigned long long ull_t;
// packed f32x2 ops (sm_103a); exact fp32 lanes
#define FMA2(d, a, b) asm("fma.rn.f32x2 %0, %1, %2, %0;" : "+l"(d) : "l"(a), "l"(b))
#define ADD2(d, a, b) asm("add.rn.f32x2 %0, %1, %2;"     : "=l"(d) : "l"(a), "l"(b))

// ---------------- device scratch ----------------
__device__ __align__(16) float g_seqs[NROW*Dc];
__device__ __align__(16) float g_qin [NROW*Dc];
__device__ __align__(16) float g_Q   [NROW*Dc];   // pre-scaled by 1/sqrt(HD)
__device__ __align__(16) float g_Kc  [NROW*Dc];   // K + bk + posK
__device__ __align__(16) float g_Vc  [NROW*Dc];   // V + bv + posV
__device__ __align__(16) float g_dqt [NROW*DQR];  // [row][h][tau]
__device__ __align__(16) __nv_bfloat16 g_tVb[NTAU*Dc]; // bf16 copy of timeV

// ---------------- K0: embedding + LN1(layer 0); tail blocks convert timeV ----------------
__global__ void __launch_bounds__(128) k_embed(const int* __restrict__ log_seqs,
                        const float* __restrict__ item_emb,
                        const float* __restrict__ g1, const float* __restrict__ b1,
                        const float* __restrict__ timeV) {
    __shared__ float r1[4], r2[4];
    int row = blockIdx.x, t = threadIdx.x;
    if (row >= NROW) { // timeV bf16 conversion tail
        int i = (row - NROW)*256 + t*2;
        if (i < NTAU*Dc) {
            float2 v = *(const float2*)&timeV[i];
            *(__nv_bfloat162*)&g_tVb[i] = __floats2bfloat162_rn(v.x, v.y);
        }
        return;
    }
    int warp = t >> 5, lane = t & 31;
    int idx = log_seqs[row];
    float v = (idx == 0) ? 0.f
                         : item_emb[idx*Dc + t] * 11.313708498984761f; // sqrt(128)
    g_seqs[row*Dc + t] = v;
    float s = v, ss = v*v;
    #pragma unroll
    for (int o = 16; o >= 1; o >>= 1) {
        s  += __shfl_xor_sync(0xffffffffu, s,  o);
        ss += __shfl_xor_sync(0xffffffffu, ss, o);
    }
    if (lane == 0) { r1[warp] = s; r2[warp] = ss; }
    __syncthreads();
    float tot  = r1[0]+r1[1]+r1[2]+r1[3];
    float tots = r2[0]+r2[1]+r2[2]+r2[3];
    float m = tot * (1.f/Dc);
    float inv = rsqrtf(tots * (1.f/Dc) - m*m + 1e-8f);
    g_qin[row*Dc + t] = (v - m) * inv * g1[t] + b1[t];
}

// ---------------- K1: QKV projections (blockIdx.y selects matrix) ----------------
__global__ void __launch_bounds__(128) k_qkv(
                      const float* __restrict__ Wq, const float* __restrict__ Wk,
                      const float* __restrict__ Wv,
                      const float* __restrict__ bq, const float* __restrict__ bk,
                      const float* __restrict__ bv,
                      const float* __restrict__ posK, const float* __restrict__ posV) {
    __shared__ __align__(16) float s_x[RQ][Dc];
    int t = threadIdx.x;
    int mat = blockIdx.y;
    int row0 = blockIdx.x * RQ;

    const float* X = (mat == 0) ? g_qin : g_seqs;
    const float* W = (mat == 0) ? Wq : (mat == 1) ? Wk : Wv;
    const float* B = (mat == 0) ? bq : (mat == 1) ? bk : bv;
    float*       O = (mat == 0) ? g_Q : (mat == 1) ? g_Kc : g_Vc;
    const float* P = (mat == 1) ? posK : posV;

    for (int i = t; i < RQ*Dc; i += 128)
        ((float*)s_x)[i] = X[row0*Dc + i];
    __syncthreads();

    float acc[RQ];
    #pragma unroll
    for (int r = 0; r < RQ; ++r) acc[r] = 0.f;

    for (int k = 0; k < Dc; k += 4) {
        float w0 = W[(k+0)*Dc + t], w1 = W[(k+1)*Dc + t];
        float w2 = W[(k+2)*Dc + t], w3 = W[(k+3)*Dc + t];
        #pragma unroll
        for (int r = 0; r < RQ; ++r) {
            float4 x = *(const float4*)&s_x[r][k];
            acc[r] = fmaf(x.x,w0, fmaf(x.y,w1, fmaf(x.z,w2, fmaf(x.w,w3, acc[r]))));
        }
    }

    float bb = B[t];
    #pragma unroll
    for (int r = 0; r < RQ; ++r) {
        int row = row0 + r;
        if (mat == 0) {
            O[row*Dc + t] = (acc[r] + bb) * SCALE;   // fold 1/sqrt(HD) into Q
        } else {
            O[row*Dc + t] = acc[r] + bb + P[(row & (Lc-1))*Dc + t];
        }
    }
}

// ---------------- K1c: dqt[row][h][tau] = Qs[row,h,:] . timeK[tau,h,:] ----------------
#define QTROWS 16
__global__ void __launch_bounds__(256, 4) k_qt(const float* __restrict__ timeK) {
    __shared__ __align__(16) float sQ[QTROWS*128];   // 8 KB
    int t = threadIdx.x;
    int w = t >> 5, lane = t & 31;
    int h = w & 3;
    int tau = blockIdx.y*64 + (w >> 2)*32 + lane;
    int r0 = blockIdx.x * QTROWS;
    bool valid = (tau < NTAU);

    float4 tr[8];
    if (valid) {
        const float4* src = (const float4*)&timeK[tau*128 + h*32];
        #pragma unroll
        for (int j = 0; j < 8; ++j) tr[j] = src[j];
    }

    { // stage 16 Q rows (coalesced): 512 float4
        const float4* src = (const float4*)&g_Q[r0*128];
        float4* dst = (float4*)sQ;
        dst[t] = src[t];
        dst[t + 256] = src[t + 256];
    }
    __syncthreads();
    if (valid) {
        for (int r = 0; r < QTROWS; r += 2) {
            const float4* qa = (const float4*)&sQ[r*128 + h*32];       // broadcast
            const float4* qb = (const float4*)&sQ[(r+1)*128 + h*32];   // broadcast
            ull_t A0 = 0, A1 = 0, B0 = 0, B1 = 0;
            #pragma unroll
            for (int j = 0; j < 8; ++j) {
                float4 qav = qa[j], qbv = qb[j];
                const ull_t* tp = reinterpret_cast<const ull_t*>(&tr[j]);
                const ull_t* ap = reinterpret_cast<const ull_t*>(&qav);
                const ull_t* bp = reinterpret_cast<const ull_t*>(&qbv);
                FMA2(A0, tp[0], ap[0]);
                FMA2(A1, tp[1], ap[1]);
                FMA2(B0, tp[0], bp[0]);
                FMA2(B1, tp[1], bp[1]);
            }
            float2 fa0 = *reinterpret_cast<float2*>(&A0);
            float2 fa1 = *reinterpret_cast<float2*>(&A1);
            float2 fb0 = *reinterpret_cast<float2*>(&B0);
            float2 fb1 = *reinterpret_cast<float2*>(&B1);
            g_dqt[(size_t)(r0 + r    )*DQR + h*NTAU + tau] = (fa0.x + fa0.y) + (fa1.x + fa1.y);
            g_dqt[(size_t)(r0 + r + 1)*DQR + h*NTAU + tau] = (fb0.x + fb0.y) + (fb1.x + fb1.y);
        }
    }
}

// ---------------- K2: tiled attention, 512 threads, f32x2 math ----------------
__global__ void __launch_bounds__(512, 4) k_attn(const int* __restrict__ time_mat) {
    extern __shared__ __align__(16) char smem_raw[];
    float* sKV = (float*)smem_raw;                 // CH*PADK = 8448 (pass1 staging; pass3 reduction)
    float* sQ  = sKV + 8448;                       // TQ2*128 = 512
    float* sS  = sQ  + 512;                        // TQ2*4*256 = 4096
    int*   s_tm = (int*)(sS + 4096);               // TQ2*256 = 1024

    int t = threadIdx.x;                           // 512
    int b  = blockIdx.x >> 6;
    int q0 = (blockIdx.x & 63) * TQ2;
    int row0 = b*Lc + q0;
    int brow = b*Lc;

    { // Q tile: 128 float4
        if (t < 128) {
            const float4* src = (const float4*)&g_Q[row0*128];
            ((float4*)sQ)[t] = src[t];
        }
    }
    { // tm tile: 256 int4
        if (t < 256) {
            const int4* src = (const int4*)&time_mat[row0*256];
            ((int4*)s_tm)[t] = src[t];
        }
    }
    { // init sS = NEGV: 1024 float4
        float4 negv = make_float4(NEGV, NEGV, NEGV, NEGV);
        float4* p = (float4*)sS;
        p[t] = negv;
        p[t + 512] = negv;
    }
    __syncthreads();

    int nkt = ((q0 + TQ2 - 1) >> 6) + 1;

    // ---- pass 1: scores; thread = (hh, q, kl); 2 heads per thread; f32x2 dots ----
    {
        int q  = (t >> 6) & 3;
        int kl = t & 63;
        int hh = t >> 8;                            // 0 or 1 (head pair)
        const float* dqp = &g_dqt[(size_t)(row0 + q)*DQR + (size_t)hh*2*NTAU];
        for (int kt = 0; kt < nkt; ++kt) {
            int k0 = kt * CH;
            { // coalesced load Kc chunk: 2048 float4, 4 per thread
                const float4* src = (const float4*)&g_Kc[(brow + k0)*128];
                float4* dst = (float4*)sKV;
                #pragma unroll
                for (int j = 0; j < 4; ++j) {
                    int f4 = t + 512*j;
                    dst[(f4 >> 5)*33 + (f4 & 31)] = src[f4];
                }
            }
            __syncthreads();
            int kg = k0 + kl;
            if (kg <= q0 + q) {
                const float4* kr = (const float4*)&sKV[kl*PADK + hh*64];
                const float4* qr = (const float4*)&sQ[q*128 + hh*64];   // broadcast
                ull_t A = 0, B = 0;
                #pragma unroll
                for (int j = 0; j < 8; ++j) {
                    float4 kv = kr[j], qv = qr[j];
                    const ull_t* kp = reinterpret_cast<const ull_t*>(&kv);
                    const ull_t* qp = reinterpret_cast<const ull_t*>(&qv);
                    FMA2(A, kp[0], qp[0]);
                    FMA2(A, kp[1], qp[1]);
                }
                #pragma unroll
                for (int j = 8; j < 16; ++j) {
                    float4 kv = kr[j], qv = qr[j];
                    const ull_t* kp = reinterpret_cast<const ull_t*>(&kv);
                    const ull_t* qp = reinterpret_cast<const ull_t*>(&qv);
                    FMA2(B, kp[0], qp[0]);
                    FMA2(B, kp[1], qp[1]);
                }
                float2 fA = *reinterpret_cast<float2*>(&A);
                float2 fB = *reinterpret_cast<float2*>(&B);
                int tau = s_tm[q*256 + kg];
                sS[(q*4 + hh*2 + 0)*256 + kg] = (fA.x + fA.y) + dqp[tau];
                sS[(q*4 + hh*2 + 1)*256 + kg] = (fB.x + fB.y) + dqp[NTAU + tau];
            }
            __syncthreads();
        }
    }

    // ---- pass 2: softmax (16 rows of 256; one warp per row) ----
    {
        int w = t >> 5, lane = t & 31;
        float* p = sS + w*256;
        float x[8];
        float mx = -3.4e38f;
        #pragma unroll
        for (int i = 0; i < 8; ++i) { x[i] = p[lane + 32*i]; mx = fmaxf(mx, x[i]); }
        #pragma unroll
        for (int o = 16; o >= 1; o >>= 1)
            mx = fmaxf(mx, __shfl_xor_sync(0xffffffffu, mx, o));
        float s = 0.f;
        #pragma unroll
        for (int i = 0; i < 8; ++i) { x[i] = expf(x[i] - mx); s += x[i]; }
        #pragma unroll
        for (int o = 16; o >= 1; o >>= 1)
            s += __shfl_xor_sync(0xffffffffu, s, o);
        float inv = 1.f / s;
        #pragma unroll
        for (int i = 0; i < 8; ++i) p[lane + 32*i] = x[i] * inv;
    }
    __syncthreads();

    // ---- pass 3: out = A @ (Vc + timeV[bf16]); 4 cols/thread, 4-way k split, f32x2 ----
    {
        int q       = t >> 7;          // 0..3
        int quarter = (t >> 5) & 3;    // 0..3: k residue class
        int colg    = t & 31;
        int col     = colg * 4;
        int h       = colg >> 3;       // head = col>>5
        int kend = q0 + q + 1;         // exact causal limit
        const float* sA  = sS + (q*4 + h)*256;
        const int*   tmq = s_tm + q*256;
        const float* vbase = &g_Vc[brow*128 + col];
        ull_t acc01 = 0, acc23 = 0;
        #pragma unroll 2
        for (int k = quarter; k < kend; k += 4) {
            float4 v4 = *(const float4*)&vbase[(size_t)k*128];   // LDG.128 coalesced
            float a = sA[k];                                      // LDS broadcast
            int tau = tmq[k];                                     // LDS broadcast
            uint2 raw = *(const uint2*)&g_tVb[tau*128 + col];     // LDG.64 (4 bf16)
            __nv_bfloat162 lo = *reinterpret_cast<__nv_bfloat162*>(&raw.x);
            __nv_bfloat162 hi = *reinterpret_cast<__nv_bfloat162*>(&raw.y);
            float2 f0 = __bfloat1622float2(lo);
            float2 f1 = __bfloat1622float2(hi);
            ull_t aa;
            asm("mov.b64 %0, {%1, %1};" : "=l"(aa) : "r"(__float_as_uint(a)));
            const ull_t* vp  = reinterpret_cast<const ull_t*>(&v4);
            const ull_t* tp0 = reinterpret_cast<const ull_t*>(&f0);
            const ull_t* tp1 = reinterpret_cast<const ull_t*>(&f1);
            ull_t s01, s23;
            ADD2(s01, vp[0], tp0[0]);
            ADD2(s23, vp[1], tp1[0]);
            FMA2(acc01, aa, s01);
            FMA2(acc23, aa, s23);
        }
        float2 a01 = *reinterpret_cast<float2*>(&acc01);
        float2 a23 = *reinterpret_cast<float2*>(&acc23);
        *(float4*)&sKV[quarter*512 + q*128 + col] = make_float4(a01.x, a01.y, a23.x, a23.y);
        __syncthreads();
        if (t < 128) {
            int qq = t >> 5, cg = (t & 31) * 4;
            int o = qq*128 + cg;
            float4 r0v = *(float4*)&sKV[o];
            float4 r1v = *(float4*)&sKV[512  + o];
            float4 r2v = *(float4*)&sKV[1024 + o];
            float4 r3v = *(float4*)&sKV[1536 + o];
            int idx = (row0 + qq)*128 + cg;
            float4 qi = *(const float4*)&g_qin[idx];
            float4 ov;
            ov.x = qi.x + ((r0v.x + r1v.x) + (r2v.x + r3v.x));
            ov.y = qi.y + ((r0v.y + r1v.y) + (r2v.y + r3v.y));
            ov.z = qi.z + ((r0v.z + r1v.z) + (r2v.z + r3v.z));
            ov.w = qi.w + ((r0v.w + r1v.w) + (r2v.w + r3v.w));
            *(float4*)&g_seqs[idx] = ov;
        }
    }
}

// ---------------- K3: LN2 + FFN + residual + pad-mask (+ LN1 of next layer) ----------------
__global__ void __launch_bounds__(128) k_ffn(const int* __restrict__ log_seqs,
                      const float* __restrict__ ln2_g, const float* __restrict__ ln2_b,
                      const float* __restrict__ W1, const float* __restrict__ b1,
                      const float* __restrict__ W2, const float* __restrict__ b2,
                      const float* __restrict__ ng, const float* __restrict__ nb) {
    __shared__ __align__(16) float s_y[RF][Dc];
    __shared__ __align__(16) float s_h[RF][Dc];
    __shared__ float s_mean[RF], s_inv[RF];
    __shared__ int   s_pad[RF];
    int t = threadIdx.x;
    int row0 = blockIdx.x * RF;
    int r = t >> 5, lane = t & 31;

    for (int i = t; i < RF*Dc; i += 128)
        ((float*)s_h)[i] = g_seqs[row0*Dc + i];
    if (t < RF) s_pad[t] = (log_seqs[row0 + t] == 0);
    __syncthreads();

    {
        float4 v4 = *(const float4*)&s_h[r][lane*4];
        float s  = v4.x + v4.y + v4.z + v4.w;
        float ss = v4.x*v4.x + v4.y*v4.y + v4.z*v4.z + v4.w*v4.w;
        #pragma unroll
        for (int o = 16; o >= 1; o >>= 1) {
            s  += __shfl_xor_sync(0xffffffffu, s,  o);
            ss += __shfl_xor_sync(0xffffffffu, ss, o);
        }
        if (lane == 0) {
            float m = s * (1.f/Dc);
            float var = ss * (1.f/Dc) - m*m;
            s_mean[r] = m;
            s_inv[r]  = rsqrtf(var + 1e-8f);
        }
    }
    __syncthreads();

    float g = ln2_g[t], bb = ln2_b[t];
    #pragma unroll
    for (int rr = 0; rr < RF; ++rr)
        s_y[rr][t] = (s_h[rr][t] - s_mean[rr]) * s_inv[rr] * g + bb;
    __syncthreads();

    float a1[RF];
    #pragma unroll
    for (int rr = 0; rr < RF; ++rr) a1[rr] = 0.f;
    for (int k = 0; k < Dc; k += 4) {
        float w0=W1[(k+0)*Dc+t], w1=W1[(k+1)*Dc+t], w2=W1[(k+2)*Dc+t], w3=W1[(k+3)*Dc+t];
        #pragma unroll
        for (int rr = 0; rr < RF; ++rr) {
            float4 y = *(const float4*)&s_y[rr][k];
            a1[rr] = fmaf(y.x,w0, fmaf(y.y,w1, fmaf(y.z,w2, fmaf(y.w,w3, a1[rr]))));
        }
    }
    float b1v = b1[t];
    __syncthreads();
    #pragma unroll
    for (int rr = 0; rr < RF; ++rr)
        s_h[rr][t] = fmaxf(a1[rr] + b1v, 0.f);
    __syncthreads();

    float a2[RF];
    #pragma unroll
    for (int rr = 0; rr < RF; ++rr) a2[rr] = 0.f;
    for (int k = 0; k < Dc; k += 4) {
        float w0=W2[(k+0)*Dc+t], w1=W2[(k+1)*Dc+t], w2=W2[(k+2)*Dc+t], w3=W2[(k+3)*Dc+t];
        #pragma unroll
        for (int rr = 0; rr < RF; ++rr) {
            float4 h4 = *(const float4*)&s_h[rr][k];
            a2[rr] = fmaf(h4.x,w0, fmaf(h4.y,w1, fmaf(h4.z,w2, fmaf(h4.w,w3, a2[rr]))));
        }
    }
    float b2v = b2[t];
    float vout[RF];
    #pragma unroll
    for (int rr = 0; rr < RF; ++rr) {
        vout[rr] = s_pad[rr] ? 0.f : (s_y[rr][t] + a2[rr] + b2v);
        g_seqs[(row0 + rr)*Dc + t] = vout[rr];
    }

    if (ng) {  // LN1 of next layer, fused
        __syncthreads();
        #pragma unroll
        for (int rr = 0; rr < RF; ++rr) s_h[rr][t] = vout[rr];
        __syncthreads();
        {
            float4 v4 = *(const float4*)&s_h[r][lane*4];
            float s  = v4.x + v4.y + v4.z + v4.w;
            float ss = v4.x*v4.x + v4.y*v4.y + v4.z*v4.z + v4.w*v4.w;
            #pragma unroll
            for (int o = 16; o >= 1; o >>= 1) {
                s  += __shfl_xor_sync(0xffffffffu, s,  o);
                ss += __shfl_xor_sync(0xffffffffu, ss, o);
            }
            if (lane == 0) {
                float m = s * (1.f/Dc);
                float var = ss * (1.f/Dc) - m*m;
                s_mean[r] = m;
                s_inv[r]  = rsqrtf(var + 1e-8f);
            }
        }
        __syncthreads();
        float gg = ng[t], bb2 = nb[t];
        #pragma unroll
        for (int rr = 0; rr < RF; ++rr)
            g_qin[(row0 + rr)*Dc + t] = (s_h[rr][t] - s_mean[rr]) * s_inv[rr] * gg + bb2;
    }
}

// ---------------- K4: final LN + pos/neg logits ----------------
__global__ void __launch_bounds__(128) k_logits(
                         const int* __restrict__ pos_seqs, const int* __restrict__ neg_seqs,
                         const float* __restrict__ item_emb,
                         const float* __restrict__ lnf_g, const float* __restrict__ lnf_b,
                         float* __restrict__ out) {
    __shared__ float r1[4], r2[4];
    int row = blockIdx.x, t = threadIdx.x;
    int warp = t >> 5, lane = t & 31;

    float x = g_seqs[row*Dc + t];
    float s = x, ss = x*x;
    #pragma unroll
    for (int o = 16; o >= 1; o >>= 1) {
        s  += __shfl_xor_sync(0xffffffffu, s,  o);
        ss += __shfl_xor_sync(0xffffffffu, ss, o);
    }
    if (lane == 0) { r1[warp] = s; r2[warp] = ss; }
    __syncthreads();
    float tot  = r1[0]+r1[1]+r1[2]+r1[3];
    float tots = r2[0]+r2[1]+r2[2]+r2[3];
    float m = tot * (1.f/Dc);
    float inv = rsqrtf(tots * (1.f/Dc) - m*m + 1e-8f);
    float f = (x - m) * inv * lnf_g[t] + lnf_b[t];

    int pi = pos_seqs[row], ni = neg_seqs[row];
    float pp = f * item_emb[pi*Dc + t];
    float nn = f * item_emb[ni*Dc + t];
    #pragma unroll
    for (int o = 16; o >= 1; o >>= 1) {
        pp += __shfl_xor_sync(0xffffffffu, pp, o);
        nn += __shfl_xor_sync(0xffffffffu, nn, o);
    }
    __syncthreads();
    if (lane == 0) { r1[warp] = pp; r2[warp] = nn; }
    __syncthreads();
    if (t == 0) {
        out[row]        = r1[0]+r1[1]+r1[2]+r1[3];
        out[NROW + row] = r2[0]+r2[1]+r2[2]+r2[3];
    }
}

// ---------------- launch ----------------
extern "C" void kernel_launch(void* const* d_in, const int* in_sizes, int n_in,
                              void* d_out, int out_size) {
    const int*   log_seqs = (const int*)  d_in[1];
    const int*   time_mat = (const int*)  d_in[2];
    const int*   pos_seqs = (const int*)  d_in[3];
    const int*   neg_seqs = (const int*)  d_in[4];
    const float* item_emb = (const float*)d_in[5];
    const float* posK     = (const float*)d_in[6];
    const float* posV     = (const float*)d_in[7];
    const float* timeK    = (const float*)d_in[8];
    const float* timeV    = (const float*)d_in[9];
    const float* ln1_g    = (const float*)d_in[10];
    const float* ln1_b    = (const float*)d_in[11];
    const float* Wq       = (const float*)d_in[12];
    const float* bq       = (const float*)d_in[13];
    const float* Wk       = (const float*)d_in[14];
    const float* bk       = (const float*)d_in[15];
    const float* Wv       = (const float*)d_in[16];
    const float* bv       = (const float*)d_in[17];
    const float* ln2_g    = (const float*)d_in[18];
    const float* ln2_b    = (const float*)d_in[19];
    const float* W1       = (const float*)d_in[20];
    const float* b1       = (const float*)d_in[21];
    const float* W2       = (const float*)d_in[22];
    const float* b2       = (const float*)d_in[23];
    const float* lnf_g    = (const float*)d_in[24];
    const float* lnf_b    = (const float*)d_in[25];
    float* out = (float*)d_out;

    cudaFuncSetAttribute(k_attn, cudaFuncAttributeMaxDynamicSharedMemorySize, SMEM_ATTN);

    k_embed<<<NROW + CVTB, 128>>>(log_seqs, item_emb, ln1_g, ln1_b, timeV);
    for (int i = 0; i < 2; ++i) {
        dim3 gq(NROW/RQ, 3);
        k_qkv<<<gq, 128>>>(Wq + i*Dc*Dc, Wk + i*Dc*Dc, Wv + i*Dc*Dc,
                           bq + i*Dc, bk + i*Dc, bv + i*Dc, posK, posV);
        dim3 gt(NROW/QTROWS, 5);          // (128, 5) = 640 blocks
        k_qt<<<gt, 256>>>(timeK);
        k_attn<<<NROW/TQ2, 512, SMEM_ATTN>>>(time_mat);
        const float* ng = (i == 0) ? (ln1_g + Dc) : nullptr;
        const float* nb = (i == 0) ? (ln1_b + Dc) : nullptr;
        k_ffn<<<NROW/RF, 128>>>(log_seqs, ln2_g + i*Dc, ln2_b + i*Dc,
                                W1 + i*Dc*Dc, b1 + i*Dc,
                                W2 + i*Dc*Dc, b2 + i*Dc, ng, nb);
    }
    k_logits<<<NROW, 128>>>(pos_seqs, neg_seqs, item_emb, lnf_g, lnf_b, out);
}